// round 3
// baseline (speedup 1.0000x reference)
#include <cuda_runtime.h>
#include <math.h>

// Problem constants (fixed by the dataset)
#define N_PTS 16384
#define HDIM  256
#define MT 16                       // rows per block in the MLP kernel
#define HTOT 384                    // concat hidden: 256 (coord) + 128 (dist)
#define GBIN 64                     // 64x64 Morton bins
#define NBIN (GBIN * GBIN)
#define TPTS 128                    // points per culling tile
#define NTILE (N_PTS / TPTS)        // 128 tiles

// Scratch (__device__ globals; no allocation allowed).
// g_binCnt is zero at module load; kscan re-zeroes it after consuming, so the
// "counts are zero when khist starts" invariant holds for every graph replay.
__device__ float  g_mean[N_PTS];
__device__ float4 g_p4[N_PTS];          // sorted {x, y, x^2+y^2, orig_idx_bits}
__device__ int    g_binCnt[NBIN];
__device__ int    g_binCursor[NBIN];
__device__ float4 g_tbox[NTILE];        // per-tile bbox {minx, miny, maxx, maxy}

// ---------------------------------------------------------------------------
// Morton binning helpers (bbox hardcoded [-60,60]; clamping only affects
// sort order, never correctness -- the kNN below is exact regardless).
// ---------------------------------------------------------------------------
__device__ __forceinline__ unsigned spread8(unsigned v) {
    v &= 0xFFu;
    v = (v | (v << 4)) & 0x0F0Fu;
    v = (v | (v << 2)) & 0x3333u;
    v = (v | (v << 1)) & 0x5555u;
    return v;
}
__device__ __forceinline__ int bin_of(float x, float y) {
    float fx = (x + 60.0f) * (GBIN / 120.0f);
    float fy = (y + 60.0f) * (GBIN / 120.0f);
    int bx = min(max(__float2int_rd(fx), 0), GBIN - 1);
    int by = min(max(__float2int_rd(fy), 0), GBIN - 1);
    return (int)(spread8((unsigned)bx) | (spread8((unsigned)by) << 1));
}

// ---------------------------------------------------------------------------
// Sort pipeline: histogram -> scan (also re-zeroes counts) -> scatter
// ---------------------------------------------------------------------------
__global__ void khist(const float2* __restrict__ pts) {
    int i = blockIdx.x * blockDim.x + threadIdx.x;
    float2 p = pts[i];
    atomicAdd(&g_binCnt[bin_of(p.x, p.y)], 1);
}

__global__ void __launch_bounds__(1024) kscan() {
    __shared__ int warpsum[32];
    const int t    = threadIdx.x;
    const int lane = t & 31;
    const int wid  = t >> 5;
    const int b0   = t * 4;

    int c0 = g_binCnt[b0 + 0];
    int c1 = g_binCnt[b0 + 1];
    int c2 = g_binCnt[b0 + 2];
    int c3 = g_binCnt[b0 + 3];
    // restore the zero invariant for the next replay
    g_binCnt[b0 + 0] = 0; g_binCnt[b0 + 1] = 0;
    g_binCnt[b0 + 2] = 0; g_binCnt[b0 + 3] = 0;
    int tot = c0 + c1 + c2 + c3;

    int v = tot;
    #pragma unroll
    for (int off = 1; off < 32; off <<= 1) {
        int n = __shfl_up_sync(0xFFFFFFFFu, v, off);
        if (lane >= off) v += n;
    }
    if (lane == 31) warpsum[wid] = v;
    __syncthreads();
    if (wid == 0) {
        int w = warpsum[lane];
        #pragma unroll
        for (int off = 1; off < 32; off <<= 1) {
            int n = __shfl_up_sync(0xFFFFFFFFu, w, off);
            if (lane >= off) w += n;
        }
        warpsum[lane] = w;
    }
    __syncthreads();

    int base = v - tot + (wid ? warpsum[wid - 1] : 0);  // exclusive prefix
    g_binCursor[b0 + 0] = base;
    g_binCursor[b0 + 1] = base + c0;
    g_binCursor[b0 + 2] = base + c0 + c1;
    g_binCursor[b0 + 3] = base + c0 + c1 + c2;
}

__global__ void kscatter(const float2* __restrict__ pts) {
    int i = blockIdx.x * blockDim.x + threadIdx.x;
    float2 p = pts[i];
    int b = bin_of(p.x, p.y);
    int pos = atomicAdd(&g_binCursor[b], 1);
    float s = fmaf(p.x, p.x, p.y * p.y);
    g_p4[pos] = make_float4(p.x, p.y, s, __int_as_float(i));
}

// ---------------------------------------------------------------------------
// Per-tile bounding boxes (tile = 128 consecutive sorted points).
// ---------------------------------------------------------------------------
__global__ void __launch_bounds__(TPTS) kbbox() {
    __shared__ float4 red[TPTS / 32];
    const int t    = blockIdx.x;
    const int lane = threadIdx.x & 31;
    const int wid  = threadIdx.x >> 5;

    float4 p = g_p4[t * TPTS + threadIdx.x];
    float mnx = p.x, mny = p.y, mxx = p.x, mxy = p.y;
    #pragma unroll
    for (int off = 16; off; off >>= 1) {
        mnx = fminf(mnx, __shfl_xor_sync(0xFFFFFFFFu, mnx, off));
        mny = fminf(mny, __shfl_xor_sync(0xFFFFFFFFu, mny, off));
        mxx = fmaxf(mxx, __shfl_xor_sync(0xFFFFFFFFu, mxx, off));
        mxy = fmaxf(mxy, __shfl_xor_sync(0xFFFFFFFFu, mxy, off));
    }
    if (lane == 0) red[wid] = make_float4(mnx, mny, mxx, mxy);
    __syncthreads();
    if (threadIdx.x == 0) {
        float4 r = red[0];
        #pragma unroll
        for (int w = 1; w < TPTS / 32; ++w) {
            float4 q = red[w];
            r.x = fminf(r.x, q.x); r.y = fminf(r.y, q.y);
            r.z = fmaxf(r.z, q.z); r.w = fmaxf(r.w, q.w);
        }
        g_tbox[t] = r;
    }
}

// ---------------------------------------------------------------------------
// Exact kNN with tile culling.
// Scan own tile first (valid upper bound t6 on the true 7th-NN distance^2),
// then only scan tiles whose bbox min-dist^2 beats some lane's t6.
// Skipped points have d2 >= bound >= true 7th value -> result exact.
// ---------------------------------------------------------------------------
#define INS7(d) do {                                                 \
    if ((d) < t6) {                                                  \
        t6 = (d); float tt;                                          \
        if (t6 < t5) { tt = t5; t5 = t6; t6 = tt; }                  \
        if (t5 < t4) { tt = t4; t4 = t5; t5 = tt; }                  \
        if (t4 < t3) { tt = t3; t3 = t4; t4 = tt; }                  \
        if (t3 < t2) { tt = t2; t2 = t3; t3 = tt; }                  \
        if (t2 < t1) { tt = t1; t1 = t2; t2 = tt; }                  \
        if (t1 < t0) { tt = t0; t0 = t1; t1 = tt; }                  \
    }                                                                \
} while (0)

__global__ void __launch_bounds__(32)
knn_tiled() {
    const int i = blockIdx.x * 32 + threadIdx.x;   // sorted row; warp = 32
    const float4 me = g_p4[i];                     // consecutive rows, one tile
    const float xi = me.x, yi = me.y;
    const int own = i >> 7;                        // uniform across the warp

    float t0 = 1e30f, t1 = 1e30f, t2 = 1e30f, t3 = 1e30f,
          t4 = 1e30f, t5 = 1e30f, t6 = 1e30f;

    // own tile: establishes the upper bound
    {
        const float4* tp = g_p4 + own * TPTS;
        #pragma unroll 4
        for (int j = 0; j < TPTS; ++j) {
            const float4 p = tp[j];
            const float dx = p.x - xi;
            const float dy = p.y - yi;
            const float d2 = fmaf(dx, dx, dy * dy);
            INS7(d2);
        }
    }

    // remaining tiles with bbox culling (warp-uniform decision)
    for (int t = 0; t < NTILE; ++t) {
        if (t == own) continue;
        const float4 b = g_tbox[t];
        const float dxm = fmaxf(fmaxf(b.x - xi, xi - b.z), 0.0f);
        const float dym = fmaxf(fmaxf(b.y - yi, yi - b.w), 0.0f);
        const float m2 = fmaf(dxm, dxm, dym * dym);
        if (__any_sync(0xFFFFFFFFu, m2 < t6)) {
            const float4* tp = g_p4 + t * TPTS;
            #pragma unroll 4
            for (int j = 0; j < TPTS; ++j) {
                const float4 p = tp[j];
                const float dx = p.x - xi;
                const float dy = p.y - yi;
                const float d2 = fmaf(dx, dx, dy * dy);
                INS7(d2);
            }
        }
    }

    // t0 is the self distance (~0); mean over the 6 real neighbours
    const float s1 = sqrtf(fmaxf(t1, 1e-12f));
    const float s2 = sqrtf(fmaxf(t2, 1e-12f));
    const float s3 = sqrtf(fmaxf(t3, 1e-12f));
    const float s4 = sqrtf(fmaxf(t4, 1e-12f));
    const float s5 = sqrtf(fmaxf(t5, 1e-12f));
    const float s6 = sqrtf(fmaxf(t6, 1e-12f));
    g_mean[__float_as_int(me.w)] =
        (s1 + s2 + s3 + s4 + s5 + s6) * (1.0f / 6.0f);
}

// ---------------------------------------------------------------------------
// Fused MLPs, packed fma.rn.f32x2, 2 output columns per thread so the
// 4 LDS.128 per k feed 16 FFMA2 (FMA-bound, not LDS-bound).
// Hidden tile transposed: hs[k*MT + m].
// ---------------------------------------------------------------------------
#define FMA2(acc, a, b) \
    asm("fma.rn.f32x2 %0, %1, %2, %0;" : "+l"(acc) : "l"(a), "l"(b))

__global__ void __launch_bounds__(128)
fused_mlp(const float2* __restrict__ coords,
          const float*  __restrict__ W1,  const float* __restrict__ b1,
          const float*  __restrict__ W2,  const float* __restrict__ b2,
          const float*  __restrict__ Wd1, const float* __restrict__ bd1,
          const float*  __restrict__ Wd2, const float* __restrict__ bd2,
          float* __restrict__ out) {
    __shared__ __align__(16) float hs[HTOT * MT];   // 24 KB, [k][m]

    const int r0 = blockIdx.x * MT;

    // Phase A: layer-1 + SiLU for MT rows x 384 concat features
    for (int e = threadIdx.x; e < HTOT * MT; e += 128) {
        const int m  = e & (MT - 1);
        const int kk = e >> 4;
        const int r  = r0 + m;
        float v;
        if (kk < HDIM) {
            const float2 c = coords[r];
            v = fmaf(c.x, W1[kk], fmaf(c.y, W1[HDIM + kk], b1[kk]));
        } else {
            const int q = kk - HDIM;
            v = fmaf(g_mean[r], Wd1[q], bd1[q]);
        }
        hs[e] = v / (1.0f + __expf(-v));
    }
    __syncthreads();

    // Phase B: two columns per thread, packed dual-row accumulation
    const int c0 = threadIdx.x;
    const int c1 = threadIdx.x + 128;
    unsigned long long accA[MT / 2], accB[MT / 2];
    {
        const float bA = b2[c0] + bd2[c0];
        const float bB = b2[c1] + bd2[c1];
        unsigned long long pA, pB;
        asm("mov.b64 %0, {%1, %1};" : "=l"(pA) : "f"(bA));
        asm("mov.b64 %0, {%1, %1};" : "=l"(pB) : "f"(bB));
        #pragma unroll
        for (int a = 0; a < MT / 2; ++a) { accA[a] = pA; accB[a] = pB; }
    }

    #pragma unroll 2
    for (int k = 0; k < HDIM; ++k) {
        const float wA = W2[k * HDIM + c0];
        const float wB = W2[k * HDIM + c1];
        unsigned long long wA2, wB2;
        asm("mov.b64 %0, {%1, %1};" : "=l"(wA2) : "f"(wA));
        asm("mov.b64 %0, {%1, %1};" : "=l"(wB2) : "f"(wB));
        const ulonglong2* hp = reinterpret_cast<const ulonglong2*>(hs + k * MT);
        #pragma unroll
        for (int p = 0; p < MT / 4; ++p) {
            const ulonglong2 h = hp[p];
            FMA2(accA[2 * p],     h.x, wA2);
            FMA2(accA[2 * p + 1], h.y, wA2);
            FMA2(accB[2 * p],     h.x, wB2);
            FMA2(accB[2 * p + 1], h.y, wB2);
        }
    }
    #pragma unroll 2
    for (int k = 0; k < HTOT - HDIM; ++k) {
        const float wA = Wd2[k * HDIM + c0];
        const float wB = Wd2[k * HDIM + c1];
        unsigned long long wA2, wB2;
        asm("mov.b64 %0, {%1, %1};" : "=l"(wA2) : "f"(wA));
        asm("mov.b64 %0, {%1, %1};" : "=l"(wB2) : "f"(wB));
        const ulonglong2* hp =
            reinterpret_cast<const ulonglong2*>(hs + (HDIM + k) * MT);
        #pragma unroll
        for (int p = 0; p < MT / 4; ++p) {
            const ulonglong2 h = hp[p];
            FMA2(accA[2 * p],     h.x, wA2);
            FMA2(accA[2 * p + 1], h.y, wA2);
            FMA2(accB[2 * p],     h.x, wB2);
            FMA2(accB[2 * p + 1], h.y, wB2);
        }
    }

    #pragma unroll
    for (int a = 0; a < MT / 2; ++a) {
        float lo, hi;
        asm("mov.b64 {%0, %1}, %2;" : "=f"(lo), "=f"(hi) : "l"(accA[a]));
        out[(size_t)(r0 + 2 * a)     * HDIM + c0] = lo;
        out[(size_t)(r0 + 2 * a + 1) * HDIM + c0] = hi;
        asm("mov.b64 {%0, %1}, %2;" : "=f"(lo), "=f"(hi) : "l"(accB[a]));
        out[(size_t)(r0 + 2 * a)     * HDIM + c1] = lo;
        out[(size_t)(r0 + 2 * a + 1) * HDIM + c1] = hi;
    }
}

// ---------------------------------------------------------------------------
// Launch. Inputs: 0 coords | 1 W1 | 2 b1 | 3 W2 | 4 b2 | 5 Wd1 | 6 bd1
//                 7 Wd2 | 8 bd2 | 9 k (fixed = 6)
// ---------------------------------------------------------------------------
extern "C" void kernel_launch(void* const* d_in, const int* in_sizes, int n_in,
                              void* d_out, int out_size) {
    const float2* coords = (const float2*)d_in[0];
    const float*  W1     = (const float*)d_in[1];
    const float*  b1     = (const float*)d_in[2];
    const float*  W2     = (const float*)d_in[3];
    const float*  b2     = (const float*)d_in[4];
    const float*  Wd1    = (const float*)d_in[5];
    const float*  bd1    = (const float*)d_in[6];
    const float*  Wd2    = (const float*)d_in[7];
    const float*  bd2    = (const float*)d_in[8];
    float* out = (float*)d_out;

    khist<<<N_PTS / 256, 256>>>(coords);
    kscan<<<1, 1024>>>();
    kscatter<<<N_PTS / 256, 256>>>(coords);
    kbbox<<<NTILE, TPTS>>>();
    knn_tiled<<<N_PTS / 32, 32>>>();
    fused_mlp<<<N_PTS / MT, 128>>>(coords, W1, b1, W2, b2,
                                   Wd1, bd1, Wd2, bd2, out);
}